// round 7
// baseline (speedup 1.0000x reference)
#include <cuda_runtime.h>

#define BB    8
#define NN    2000000
#define TOTAL (BB * NN)          // 16,000,000
#define NCLS  16
#define NGRP  (BB * NCLS)        // 128

#define BITMAP_WORDS (1u << 23)          // 2^23 u32 = 2^28 bits = 32MB
#define BITIDX_MASK  ((1u << 28) - 1)
#define HLOG   22
#define HSLOTS (1u << HLOG)              // 4M slots * 8B = 32MB
#define HMASK  (HSLOTS - 1)
#define OCCBIT (1ull << 63)
#define KEYMASK ((((1ull << 39) - 1)) | OCCBIT)   // key(39b) + occupied bit
#define CNTONE  (1ull << 39)                      // count in bits [39,63)
#define LISTCAP (1u << 20)                        // 1M entries, 4MB

// ---------------- scratch (static device globals; no allocation) ------------
__device__ __align__(16) unsigned int        g_bitmap[BITMAP_WORDS];
__device__ __align__(16) unsigned long long  g_hash[HSLOTS];
__device__ double             g_sum[NGRP];
__device__ unsigned int       g_cntg[NGRP];
__device__ unsigned int       g_minord[NGRP];
__device__ unsigned long long g_packed[NGRP];
__device__ unsigned int       g_nlist;
__device__ unsigned int       g_list[LISTCAP];    // slot indices of true dups

// ---------------- helpers ----------------
__device__ __forceinline__ unsigned long long mix64(unsigned long long h) {
    h += 0x9E3779B97F4A7C15ull;
    h ^= h >> 30; h *= 0xBF58476D1CE4E5B9ull;
    h ^= h >> 27; h *= 0x94D049BB133111EBull;
    h ^= h >> 31;
    return h;
}
// order-preserving map float-bits -> u32 (smaller float => smaller uint)
__device__ __forceinline__ unsigned int orderf(unsigned int u) {
    return u ^ ((u & 0x80000000u) ? 0xFFFFFFFFu : 0x80000000u);
}

// ---------------- K0a/K0b: clear scratch (split for ncu targeting) ----------
__global__ void k_clear_bm() {
    unsigned tid    = blockIdx.x * blockDim.x + threadIdx.x;
    unsigned stride = gridDim.x * blockDim.x;
    uint4 z = make_uint4(0u, 0u, 0u, 0u);
    uint4* bm = reinterpret_cast<uint4*>(g_bitmap);
    for (unsigned i = tid; i < BITMAP_WORDS / 4; i += stride) bm[i] = z;
}
__global__ void k_clear_hash() {
    unsigned tid    = blockIdx.x * blockDim.x + threadIdx.x;
    unsigned stride = gridDim.x * blockDim.x;
    uint4 z = make_uint4(0u, 0u, 0u, 0u);
    uint4* hh = reinterpret_cast<uint4*>(g_hash);
    for (unsigned i = tid; i < HSLOTS / 2; i += stride) hh[i] = z;
    if (tid < NGRP) {
        g_sum[tid]    = 0.0;
        g_cntg[tid]   = 0u;
        g_minord[tid] = 0xFFFFFFFFu;
        g_packed[tid] = 0ull;
    }
    if (tid == 0) g_nlist = 0u;
}

// ---------------- K1: lean bitmap filter + candidate insert ----------------
__device__ __forceinline__ void insert_candidate(unsigned long long key,
                                                 unsigned long long h) {
    unsigned idx = (unsigned)(h >> 32) & HMASK;
    unsigned long long tag = key | OCCBIT;
    for (;;) {
        unsigned long long cur = __ldcg(&g_hash[idx]);
        if (cur == 0ull) {
            unsigned long long old = atomicCAS(&g_hash[idx], 0ull, tag);
            if (old == 0ull) return;
            cur = old;
        }
        if (((cur ^ tag) & KEYMASK) == 0ull) return;   // already inserted
        idx = (idx + 1) & HMASK;
    }
}

__global__ void __launch_bounds__(256) k_filter(const float* __restrict__ x,
                                                const int* __restrict__ t) {
    const float4* x4 = reinterpret_cast<const float4*>(x);
    const int4*   t4 = reinterpret_cast<const int4*>(t);
    unsigned stride = gridDim.x * blockDim.x;
    for (unsigned i = blockIdx.x * blockDim.x + threadIdx.x; i < TOTAL / 8;
         i += stride) {
        unsigned b  = (i * 8u) / NN;       // 8-elem chunk never crosses batch
        unsigned gb = b * NCLS;
        float4 xa = __ldcs(x4 + 2 * i), xb = __ldcs(x4 + 2 * i + 1);
        int4   ta = __ldcs(t4 + 2 * i), tb = __ldcs(t4 + 2 * i + 1);
        float vs[8] = {xa.x, xa.y, xa.z, xa.w, xb.x, xb.y, xb.z, xb.w};
        int   cs[8] = {ta.x, ta.y, ta.z, ta.w, tb.x, tb.y, tb.z, tb.w};
        unsigned long long keys[8], hs[8];
        unsigned words[8], bits[8], olds[8];
#pragma unroll
        for (int j = 0; j < 8; j++) {
            unsigned u = __float_as_uint(vs[j]);
            unsigned long long key =
                ((unsigned long long)(gb + (unsigned)cs[j]) << 32) | u;
            keys[j] = key;
            unsigned long long h = mix64(key);
            hs[j] = h;
            unsigned bi = (unsigned)h & BITIDX_MASK;
            words[j] = bi >> 5;
            bits[j]  = 1u << (bi & 31);
        }
#pragma unroll
        for (int j = 0; j < 8; j++)
            olds[j] = atomicOr(&g_bitmap[words[j]], bits[j]);   // 8 in flight
#pragma unroll
        for (int j = 0; j < 8; j++)
            if (olds[j] & bits[j]) insert_candidate(keys[j], hs[j]);
    }
}

// ---------------- K2: probe/count + group stats + dup-list ----------------
#define P3_TPB    128
#define P3_CHUNK  8192
#define BLKS_PER_B ((NN + P3_CHUNK - 1) / P3_CHUNK)   // 245

__device__ __forceinline__ void probe_resolve(unsigned long long key,
                                              unsigned idx,
                                              unsigned long long cur) {
    unsigned long long tag = key | OCCBIT;
    for (;;) {
        if (cur == 0ull) return;                       // not a candidate
        if (((cur ^ tag) & KEYMASK) == 0ull) {
            unsigned long long old = atomicAdd(&g_hash[idx], CNTONE);
            // exactly-once append when count transitions 1 -> 2 (true dup)
            if (((old >> 39) & 0xFFFFFFull) == 1ull) {
                unsigned pos = atomicAdd(&g_nlist, 1u);
                if (pos < LISTCAP) g_list[pos] = idx;
            }
            return;
        }
        idx = (idx + 1) & HMASK;
        cur = __ldg(&g_hash[idx]);
    }
}

__global__ void __launch_bounds__(P3_TPB) k_probe_stats(
    const float* __restrict__ x, const int* __restrict__ t) {
    // [class][thread] layout -> conflict-free for any class mix
    __shared__ float          s_sum[NCLS * P3_TPB];
    __shared__ unsigned short s_cnt[NCLS * P3_TPB];   // <=64 elems/thread
    __shared__ unsigned int   s_min[NCLS * P3_TPB];

    const int tx = threadIdx.x;
    const int b  = blockIdx.y;
    const unsigned gbase = (unsigned)b * NCLS;

#pragma unroll
    for (int c = 0; c < NCLS; c++) {
        s_sum[c * P3_TPB + tx] = 0.f;
        s_cnt[c * P3_TPB + tx] = 0;
        s_min[c * P3_TPB + tx] = 0xFFFFFFFFu;
    }
    __syncthreads();

    long long base = (long long)b * NN + (long long)blockIdx.x * P3_CHUNK;
    int nelem = NN - blockIdx.x * P3_CHUNK;
    if (nelem > P3_CHUNK) nelem = P3_CHUNK;
    int nv = nelem >> 3;   // 8-wide

    const float4* x4 = reinterpret_cast<const float4*>(x + base);
    const int4*   t4 = reinterpret_cast<const int4*>(t + base);

    for (int i = tx; i < nv; i += P3_TPB) {
        float4 xa = __ldcs(x4 + 2 * i), xb = __ldcs(x4 + 2 * i + 1);
        int4   ta = __ldcs(t4 + 2 * i), tb = __ldcs(t4 + 2 * i + 1);
        float vs[8] = {xa.x, xa.y, xa.z, xa.w, xb.x, xb.y, xb.z, xb.w};
        int   cs[8] = {ta.x, ta.y, ta.z, ta.w, tb.x, tb.y, tb.z, tb.w};

        unsigned long long keys[8], curs[8];
        unsigned idxs[8];
#pragma unroll
        for (int j = 0; j < 8; j++) {
            unsigned u = __float_as_uint(vs[j]);
            unsigned long long key =
                ((unsigned long long)(gbase + (unsigned)cs[j]) << 32) | u;
            keys[j] = key;
            unsigned long long h = mix64(key);
            idxs[j] = (unsigned)(h >> 32) & HMASK;
        }
#pragma unroll
        for (int j = 0; j < 8; j++)
            curs[j] = __ldg(&g_hash[idxs[j]]);         // 8 probes in flight
#pragma unroll
        for (int j = 0; j < 8; j++) {
            // stats (conflict-free smem) hidden under probe latency
            int s = cs[j] * P3_TPB + tx;
            s_sum[s] += vs[j];
            s_cnt[s] = (unsigned short)(s_cnt[s] + 1);
            unsigned ov = orderf(__float_as_uint(vs[j]));
            if (ov < s_min[s]) s_min[s] = ov;
            probe_resolve(keys[j], idxs[j], curs[j]);
        }
    }
    __syncthreads();

    // block reduce per class
    __shared__ float        r_sum[P3_TPB / 32][NCLS];
    __shared__ unsigned int r_cnt[P3_TPB / 32][NCLS];
    __shared__ unsigned int r_min[P3_TPB / 32][NCLS];
    const int lane = tx & 31, warp = tx >> 5;
#pragma unroll
    for (int c = 0; c < NCLS; c++) {
        float    sv = s_sum[c * P3_TPB + tx];
        unsigned cv = s_cnt[c * P3_TPB + tx];
        unsigned mv = s_min[c * P3_TPB + tx];
#pragma unroll
        for (int o = 16; o > 0; o >>= 1) {
            sv += __shfl_down_sync(0xFFFFFFFFu, sv, o);
            cv += __shfl_down_sync(0xFFFFFFFFu, cv, o);
            unsigned m2 = __shfl_down_sync(0xFFFFFFFFu, mv, o);
            mv = mv < m2 ? mv : m2;
        }
        if (lane == 0) { r_sum[warp][c] = sv; r_cnt[warp][c] = cv; r_min[warp][c] = mv; }
    }
    __syncthreads();
    if (tx < NCLS) {
        float    sv = 0.f; unsigned cv = 0u; unsigned mv = 0xFFFFFFFFu;
#pragma unroll
        for (int w = 0; w < P3_TPB / 32; w++) {
            sv += r_sum[w][tx];
            cv += r_cnt[w][tx];
            mv = mv < r_min[w][tx] ? mv : r_min[w][tx];
        }
        atomicAdd(&g_sum[gbase + tx], (double)sv);
        atomicAdd(&g_cntg[gbase + tx], cv);
        atomicMin(&g_minord[gbase + tx], mv);
    }
}

// ---------------- K3: modes from dup-list (smem pre-reduction) -------------
__device__ __forceinline__ void mode_update_s(unsigned long long cur,
                                              unsigned long long* s_pk) {
    unsigned cnt = (unsigned)((cur >> 39) & 0xFFFFFFu);
    if (cnt >= 2u) {
        unsigned grp = (unsigned)((cur >> 32) & 0x7Fu);
        unsigned u   = (unsigned)(cur & 0xFFFFFFFFull);
        unsigned ov  = orderf(u);
        unsigned long long packed =
            ((unsigned long long)cnt << 32) | (unsigned long long)(~ov);
        atomicMax(&s_pk[grp], packed);
    }
}

#define MODES_TPB 256
#define MODES_BLK 256

__global__ void __launch_bounds__(MODES_TPB) k_modes() {
    __shared__ unsigned long long s_pk[NGRP];
    if (threadIdx.x < NGRP) s_pk[threadIdx.x] = 0ull;
    __syncthreads();

    unsigned n = g_nlist;
    unsigned stride = gridDim.x * blockDim.x;
    if (n <= LISTCAP) {
        for (unsigned i = blockIdx.x * blockDim.x + threadIdx.x; i < n;
             i += stride)
            mode_update_s(__ldcg(&g_hash[g_list[i]]), s_pk);
    } else {
        // fallback: list overflowed -> scan the whole table (always correct)
        for (unsigned i = blockIdx.x * blockDim.x + threadIdx.x; i < HSLOTS;
             i += stride)
            mode_update_s(__ldcs(&g_hash[i]), s_pk);
    }
    __syncthreads();
    if (threadIdx.x < NGRP) {
        unsigned long long v = s_pk[threadIdx.x];
        if (v != 0ull) atomicMax(&g_packed[threadIdx.x], v);
    }
}

// ---------------- K4: final scalar ----------------
__global__ void k_final(float* __restrict__ out) {
    __shared__ double red[128];
    int g = threadIdx.x;
    double contrib = 0.0;
    if (g < NGRP) {
        unsigned cnt = g_cntg[g];
        if (cnt > 0u) {
            double mean = g_sum[g] / (double)cnt;
            unsigned long long packed = g_packed[g];
            unsigned ov;
            if (packed != 0ull) {
                ov = ~((unsigned)(packed & 0xFFFFFFFFull));   // dup mode
            } else {
                ov = g_minord[g];                              // all counts == 1
            }
            unsigned u = (ov & 0x80000000u) ? (ov ^ 0x80000000u) : ~ov;
            float mode = __uint_as_float(u);
            contrib = (double)cnt * (mean - (double)mode);
        }
    }
    red[threadIdx.x] = contrib;
    __syncthreads();
    for (int s = 64; s > 0; s >>= 1) {
        if (threadIdx.x < s) red[threadIdx.x] += red[threadIdx.x + s];
        __syncthreads();
    }
    if (threadIdx.x == 0) out[0] = (float)(red[0] / (double)TOTAL);
}

// ---------------- launch ----------------
extern "C" void kernel_launch(void* const* d_in, const int* in_sizes, int n_in,
                              void* d_out, int out_size) {
    const float* x = (const float*)d_in[0];
    const int*   t = (const int*)d_in[1];
    float* out = (float*)d_out;

    k_clear_bm<<<8192, 256>>>();
    k_clear_hash<<<8192, 256>>>();
    k_filter<<<4096, 256>>>(x, t);
    dim3 g3(BLKS_PER_B, BB);
    k_probe_stats<<<g3, P3_TPB>>>(x, t);      // 4th launch -> ncu captures this
    k_modes<<<MODES_BLK, MODES_TPB>>>();
    k_final<<<1, 128>>>(out);
}

// round 8
// speedup vs baseline: 1.2332x; 1.2332x over previous
#include <cuda_runtime.h>

#define BB    8
#define NN    2000000
#define TOTAL (BB * NN)          // 16,000,000
#define NCLS  16
#define NGRP  (BB * NCLS)        // 128

#define BITMAP_WORDS (1u << 23)          // 2^23 u32 = 2^28 bits = 32MB
#define BITIDX_MASK  ((1u << 28) - 1)
#define HLOG   22
#define HSLOTS (1u << HLOG)              // 4M slots * 8B = 32MB
#define HMASK  (HSLOTS - 1)
#define OCCBIT (1ull << 63)
#define KEYMASK ((((1ull << 39) - 1)) | OCCBIT)   // key(39b) + occupied bit
#define CNTONE  (1ull << 39)                      // count in bits [39,63)
#define LISTCAP (1u << 20)                        // 1M entries, 4MB

// ---------------- scratch (static device globals; no allocation) ------------
__device__ __align__(16) unsigned int        g_bitmap[BITMAP_WORDS];
__device__ __align__(16) unsigned long long  g_hash[HSLOTS];
__device__ double             g_sum[NGRP];
__device__ unsigned int       g_cntg[NGRP];
__device__ unsigned int       g_minord[NGRP];
__device__ unsigned long long g_packed[NGRP];
__device__ unsigned int       g_nlist;
__device__ unsigned int       g_list[LISTCAP];    // slot indices of true dups

// ---------------- helpers ----------------
__device__ __forceinline__ unsigned long long mix64(unsigned long long h) {
    h += 0x9E3779B97F4A7C15ull;
    h ^= h >> 30; h *= 0xBF58476D1CE4E5B9ull;
    h ^= h >> 27; h *= 0x94D049BB133111EBull;
    h ^= h >> 31;
    return h;
}
// order-preserving map float-bits -> u32 (smaller float => smaller uint)
__device__ __forceinline__ unsigned int orderf(unsigned int u) {
    return u ^ ((u & 0x80000000u) ? 0xFFFFFFFFu : 0x80000000u);
}

// ------- K0a/K0b/K0c: clear scratch (3 launches so k_filter is 4th) --------
__global__ void k_clear_bm() {
    unsigned tid    = blockIdx.x * blockDim.x + threadIdx.x;
    unsigned stride = gridDim.x * blockDim.x;
    uint4 z = make_uint4(0u, 0u, 0u, 0u);
    uint4* bm = reinterpret_cast<uint4*>(g_bitmap);
    for (unsigned i = tid; i < BITMAP_WORDS / 4; i += stride) bm[i] = z;
}
__global__ void k_clear_hash_lo() {
    unsigned tid    = blockIdx.x * blockDim.x + threadIdx.x;
    unsigned stride = gridDim.x * blockDim.x;
    uint4 z = make_uint4(0u, 0u, 0u, 0u);
    uint4* hh = reinterpret_cast<uint4*>(g_hash);
    for (unsigned i = tid; i < HSLOTS / 4; i += stride) hh[i] = z;
}
__global__ void k_clear_hash_hi() {
    unsigned tid    = blockIdx.x * blockDim.x + threadIdx.x;
    unsigned stride = gridDim.x * blockDim.x;
    uint4 z = make_uint4(0u, 0u, 0u, 0u);
    uint4* hh = reinterpret_cast<uint4*>(g_hash) + HSLOTS / 4;
    for (unsigned i = tid; i < HSLOTS / 4; i += stride) hh[i] = z;
    if (tid < NGRP) {
        g_sum[tid]    = 0.0;
        g_cntg[tid]   = 0u;
        g_minord[tid] = 0xFFFFFFFFu;
        g_packed[tid] = 0ull;
    }
    if (tid == 0) g_nlist = 0u;
}

// ---------------- K1: lean bitmap filter + candidate insert ----------------
__device__ __forceinline__ void insert_candidate(unsigned long long key,
                                                 unsigned long long h) {
    unsigned idx = (unsigned)(h >> 32) & HMASK;
    unsigned long long tag = key | OCCBIT;
    for (;;) {
        unsigned long long cur = __ldcg(&g_hash[idx]);
        if (cur == 0ull) {
            unsigned long long old = atomicCAS(&g_hash[idx], 0ull, tag);
            if (old == 0ull) return;
            cur = old;
        }
        if (((cur ^ tag) & KEYMASK) == 0ull) return;   // already inserted
        idx = (idx + 1) & HMASK;
    }
}

__global__ void __launch_bounds__(256) k_filter(const float* __restrict__ x,
                                                const int* __restrict__ t) {
    const float4* x4 = reinterpret_cast<const float4*>(x);
    const int4*   t4 = reinterpret_cast<const int4*>(t);
    unsigned stride = gridDim.x * blockDim.x;
    unsigned i = blockIdx.x * blockDim.x + threadIdx.x;

    float4 xa, xb; int4 ta, tb;
    if (i < TOTAL / 8) {
        xa = __ldcs(x4 + 2 * i); xb = __ldcs(x4 + 2 * i + 1);
        ta = __ldcs(t4 + 2 * i); tb = __ldcs(t4 + 2 * i + 1);
    }
    for (; i < TOTAL / 8; i += stride) {
        unsigned b  = (i * 8u) / NN;       // 8-elem chunk never crosses batch
        unsigned gb = b * NCLS;
        float vs[8] = {xa.x, xa.y, xa.z, xa.w, xb.x, xb.y, xb.z, xb.w};
        int   cs[8] = {ta.x, ta.y, ta.z, ta.w, tb.x, tb.y, tb.z, tb.w};
        unsigned long long keys[8], hs[8];
        unsigned words[8], bits[8], olds[8];
#pragma unroll
        for (int j = 0; j < 8; j++) {
            unsigned u = __float_as_uint(vs[j]);
            unsigned long long key =
                ((unsigned long long)(gb + (unsigned)cs[j]) << 32) | u;
            keys[j] = key;
            unsigned long long h = mix64(key);
            hs[j] = h;
            unsigned bi = (unsigned)h & BITIDX_MASK;
            words[j] = bi >> 5;
            bits[j]  = 1u << (bi & 31);
        }
#pragma unroll
        for (int j = 0; j < 8; j++)
            olds[j] = atomicOr(&g_bitmap[words[j]], bits[j]);   // 8 in flight
        // prefetch next iteration's inputs under the atomic latency
        unsigned inext = i + stride;
        if (inext < TOTAL / 8) {
            xa = __ldcs(x4 + 2 * inext); xb = __ldcs(x4 + 2 * inext + 1);
            ta = __ldcs(t4 + 2 * inext); tb = __ldcs(t4 + 2 * inext + 1);
        }
#pragma unroll
        for (int j = 0; j < 8; j++)
            if (olds[j] & bits[j]) insert_candidate(keys[j], hs[j]);
    }
}

// ---------------- K2: pipelined probe/count + group stats ------------------
#define P3_TPB    128
#define P3_CHUNK  8192
#define BLKS_PER_B ((NN + P3_CHUNK - 1) / P3_CHUNK)   // 245

__device__ __forceinline__ void probe_resolve(unsigned long long key,
                                              unsigned idx,
                                              unsigned long long cur) {
    unsigned long long tag = key | OCCBIT;
    for (;;) {
        if (cur == 0ull) return;                       // not a candidate
        if (((cur ^ tag) & KEYMASK) == 0ull) {
            unsigned long long old = atomicAdd(&g_hash[idx], CNTONE);
            // exactly-once append when count transitions 1 -> 2 (true dup)
            if (((old >> 39) & 0xFFFFFFull) == 1ull) {
                unsigned pos = atomicAdd(&g_nlist, 1u);
                if (pos < LISTCAP) g_list[pos] = idx;
            }
            return;
        }
        idx = (idx + 1) & HMASK;
        cur = __ldg(&g_hash[idx]);
    }
}

__global__ void __launch_bounds__(P3_TPB) k_probe_stats(
    const float* __restrict__ x, const int* __restrict__ t) {
    // [class][thread] layout -> conflict-free for any class mix
    __shared__ float         s_sum[NCLS * P3_TPB];   // 8KB
    __shared__ unsigned char s_cnt[NCLS * P3_TPB];   // 2KB (<=64/thread)
    __shared__ unsigned int  s_min[NCLS * P3_TPB];   // 8KB

    const int tx = threadIdx.x;
    const int b  = blockIdx.y;
    const unsigned gbase = (unsigned)b * NCLS;

#pragma unroll
    for (int c = 0; c < NCLS; c++) {
        s_sum[c * P3_TPB + tx] = 0.f;
        s_cnt[c * P3_TPB + tx] = 0;
        s_min[c * P3_TPB + tx] = 0xFFFFFFFFu;
    }
    __syncthreads();

    long long base = (long long)b * NN + (long long)blockIdx.x * P3_CHUNK;
    int nelem = NN - blockIdx.x * P3_CHUNK;
    if (nelem > P3_CHUNK) nelem = P3_CHUNK;
    int nv = nelem >> 3;   // 8-wide batches

    const float4* x4 = reinterpret_cast<const float4*>(x + base);
    const int4*   t4 = reinterpret_cast<const int4*>(t + base);

    float4 xa, xb; int4 ta, tb;
    if (tx < nv) {
        xa = __ldcs(x4 + 2 * tx); xb = __ldcs(x4 + 2 * tx + 1);
        ta = __ldcs(t4 + 2 * tx); tb = __ldcs(t4 + 2 * tx + 1);
    }
    for (int i = tx; i < nv; i += P3_TPB) {
        float vs[8] = {xa.x, xa.y, xa.z, xa.w, xb.x, xb.y, xb.z, xb.w};
        int   cs[8] = {ta.x, ta.y, ta.z, ta.w, tb.x, tb.y, tb.z, tb.w};

        unsigned long long keys[8], curs[8];
        unsigned idxs[8];
#pragma unroll
        for (int j = 0; j < 8; j++) {
            unsigned u = __float_as_uint(vs[j]);
            unsigned long long key =
                ((unsigned long long)(gbase + (unsigned)cs[j]) << 32) | u;
            keys[j] = key;
            unsigned long long h = mix64(key);
            idxs[j] = (unsigned)(h >> 32) & HMASK;
        }
#pragma unroll
        for (int j = 0; j < 8; j++)
            curs[j] = __ldg(&g_hash[idxs[j]]);         // 8 probes in flight

        // prefetch next iteration's inputs under probe latency
        int inext = i + P3_TPB;
        if (inext < nv) {
            xa = __ldcs(x4 + 2 * inext); xb = __ldcs(x4 + 2 * inext + 1);
            ta = __ldcs(t4 + 2 * inext); tb = __ldcs(t4 + 2 * inext + 1);
        }
#pragma unroll
        for (int j = 0; j < 8; j++) {
            // stats (conflict-free smem) hidden under probe latency
            int s = cs[j] * P3_TPB + tx;
            s_sum[s] += vs[j];
            s_cnt[s] = (unsigned char)(s_cnt[s] + 1);
            unsigned ov = orderf(__float_as_uint(vs[j]));
            if (ov < s_min[s]) s_min[s] = ov;
            probe_resolve(keys[j], idxs[j], curs[j]);
        }
    }
    __syncthreads();

    // block reduce per class
    __shared__ float        r_sum[P3_TPB / 32][NCLS];
    __shared__ unsigned int r_cnt[P3_TPB / 32][NCLS];
    __shared__ unsigned int r_min[P3_TPB / 32][NCLS];
    const int lane = tx & 31, warp = tx >> 5;
#pragma unroll
    for (int c = 0; c < NCLS; c++) {
        float    sv = s_sum[c * P3_TPB + tx];
        unsigned cv = s_cnt[c * P3_TPB + tx];
        unsigned mv = s_min[c * P3_TPB + tx];
#pragma unroll
        for (int o = 16; o > 0; o >>= 1) {
            sv += __shfl_down_sync(0xFFFFFFFFu, sv, o);
            cv += __shfl_down_sync(0xFFFFFFFFu, cv, o);
            unsigned m2 = __shfl_down_sync(0xFFFFFFFFu, mv, o);
            mv = mv < m2 ? mv : m2;
        }
        if (lane == 0) { r_sum[warp][c] = sv; r_cnt[warp][c] = cv; r_min[warp][c] = mv; }
    }
    __syncthreads();
    if (tx < NCLS) {
        float    sv = 0.f; unsigned cv = 0u; unsigned mv = 0xFFFFFFFFu;
#pragma unroll
        for (int w = 0; w < P3_TPB / 32; w++) {
            sv += r_sum[w][tx];
            cv += r_cnt[w][tx];
            mv = mv < r_min[w][tx] ? mv : r_min[w][tx];
        }
        atomicAdd(&g_sum[gbase + tx], (double)sv);
        atomicAdd(&g_cntg[gbase + tx], cv);
        atomicMin(&g_minord[gbase + tx], mv);
    }
}

// ---------------- K3: modes from dup-list (smem pre-reduction) -------------
__device__ __forceinline__ void mode_update_s(unsigned long long cur,
                                              unsigned long long* s_pk) {
    unsigned cnt = (unsigned)((cur >> 39) & 0xFFFFFFu);
    if (cnt >= 2u) {
        unsigned grp = (unsigned)((cur >> 32) & 0x7Fu);
        unsigned u   = (unsigned)(cur & 0xFFFFFFFFull);
        unsigned ov  = orderf(u);
        unsigned long long packed =
            ((unsigned long long)cnt << 32) | (unsigned long long)(~ov);
        atomicMax(&s_pk[grp], packed);
    }
}

#define MODES_TPB 256
#define MODES_BLK 256

__global__ void __launch_bounds__(MODES_TPB) k_modes() {
    __shared__ unsigned long long s_pk[NGRP];
    if (threadIdx.x < NGRP) s_pk[threadIdx.x] = 0ull;
    __syncthreads();

    unsigned n = g_nlist;
    unsigned stride = gridDim.x * blockDim.x;
    if (n <= LISTCAP) {
        for (unsigned i = blockIdx.x * blockDim.x + threadIdx.x; i < n;
             i += stride)
            mode_update_s(__ldcg(&g_hash[g_list[i]]), s_pk);
    } else {
        // fallback: list overflowed -> scan the whole table (always correct)
        for (unsigned i = blockIdx.x * blockDim.x + threadIdx.x; i < HSLOTS;
             i += stride)
            mode_update_s(__ldcs(&g_hash[i]), s_pk);
    }
    __syncthreads();
    if (threadIdx.x < NGRP) {
        unsigned long long v = s_pk[threadIdx.x];
        if (v != 0ull) atomicMax(&g_packed[threadIdx.x], v);
    }
}

// ---------------- K4: final scalar ----------------
__global__ void k_final(float* __restrict__ out) {
    __shared__ double red[128];
    int g = threadIdx.x;
    double contrib = 0.0;
    if (g < NGRP) {
        unsigned cnt = g_cntg[g];
        if (cnt > 0u) {
            double mean = g_sum[g] / (double)cnt;
            unsigned long long packed = g_packed[g];
            unsigned ov;
            if (packed != 0ull) {
                ov = ~((unsigned)(packed & 0xFFFFFFFFull));   // dup mode
            } else {
                ov = g_minord[g];                              // all counts == 1
            }
            unsigned u = (ov & 0x80000000u) ? (ov ^ 0x80000000u) : ~ov;
            float mode = __uint_as_float(u);
            contrib = (double)cnt * (mean - (double)mode);
        }
    }
    red[threadIdx.x] = contrib;
    __syncthreads();
    for (int s = 64; s > 0; s >>= 1) {
        if (threadIdx.x < s) red[threadIdx.x] += red[threadIdx.x + s];
        __syncthreads();
    }
    if (threadIdx.x == 0) out[0] = (float)(red[0] / (double)TOTAL);
}

// ---------------- launch ----------------
extern "C" void kernel_launch(void* const* d_in, const int* in_sizes, int n_in,
                              void* d_out, int out_size) {
    const float* x = (const float*)d_in[0];
    const int*   t = (const int*)d_in[1];
    float* out = (float*)d_out;

    k_clear_bm<<<4096, 256>>>();
    k_clear_hash_lo<<<4096, 256>>>();
    k_clear_hash_hi<<<4096, 256>>>();
    k_filter<<<4096, 256>>>(x, t);            // 4th launch -> ncu captures this
    dim3 g3(BLKS_PER_B, BB);
    k_probe_stats<<<g3, P3_TPB>>>(x, t);
    k_modes<<<MODES_BLK, MODES_TPB>>>();
    k_final<<<1, 128>>>(out);
}

// round 10
// speedup vs baseline: 1.2798x; 1.0378x over previous
#include <cuda_runtime.h>

#define BB    8
#define NN    2000000
#define TOTAL (BB * NN)          // 16,000,000
#define NCLS  16
#define NGRP  (BB * NCLS)        // 128

#define BITMAP_WORDS (1u << 23)          // 2^23 u32 = 2^28 bits = 32MB
#define BITIDX_MASK  ((1u << 28) - 1)
#define HLOG   22
#define HSLOTS (1u << HLOG)              // 4M slots * 8B = 32MB
#define HMASK  (HSLOTS - 1)
#define OCCBIT (1ull << 63)
#define KEYMASK ((((1ull << 39) - 1)) | OCCBIT)   // key(39b) + occupied bit
#define CNTONE  (1ull << 39)                      // count in bits [39,63)
#define LISTCAP (1u << 20)                        // 1M entries, 4MB

// ---------------- scratch (static device globals; no allocation) ------------
__device__ __align__(16) unsigned int        g_bitmap[BITMAP_WORDS];
__device__ __align__(16) unsigned long long  g_hash[HSLOTS];
__device__ double             g_sum[NGRP];
__device__ unsigned int       g_cntg[NGRP];
__device__ unsigned int       g_minord[NGRP];
__device__ unsigned long long g_packed[NGRP];
__device__ unsigned int       g_nlist;
__device__ unsigned int       g_list[LISTCAP];    // slot indices of true dups

// ---------------- helpers ----------------
__device__ __forceinline__ unsigned long long mix64(unsigned long long h) {
    h += 0x9E3779B97F4A7C15ull;
    h ^= h >> 30; h *= 0xBF58476D1CE4E5B9ull;
    h ^= h >> 27; h *= 0x94D049BB133111EBull;
    h ^= h >> 31;
    return h;
}
// order-preserving map float-bits -> u32 (smaller float => smaller uint)
__device__ __forceinline__ unsigned int orderf(unsigned int u) {
    return u ^ ((u & 0x80000000u) ? 0xFFFFFFFFu : 0x80000000u);
}
__device__ __forceinline__ unsigned long long make_key(unsigned gb, int c,
                                                       float v) {
    return ((unsigned long long)(gb + (unsigned)c) << 32) | __float_as_uint(v);
}

// ---------------- K0a/K0b: clear scratch ----------------
__global__ void k_clear_bm() {
    unsigned tid    = blockIdx.x * blockDim.x + threadIdx.x;
    unsigned stride = gridDim.x * blockDim.x;
    uint4 z = make_uint4(0u, 0u, 0u, 0u);
    uint4* bm = reinterpret_cast<uint4*>(g_bitmap);
    for (unsigned i = tid; i < BITMAP_WORDS / 4; i += stride) bm[i] = z;
}
__global__ void k_clear_hash() {
    unsigned tid    = blockIdx.x * blockDim.x + threadIdx.x;
    unsigned stride = gridDim.x * blockDim.x;
    uint4 z = make_uint4(0u, 0u, 0u, 0u);
    uint4* hh = reinterpret_cast<uint4*>(g_hash);
    for (unsigned i = tid; i < HSLOTS / 2; i += stride) hh[i] = z;
    if (tid < NGRP) {
        g_sum[tid]    = 0.0;
        g_cntg[tid]   = 0u;
        g_minord[tid] = 0xFFFFFFFFu;
        g_packed[tid] = 0ull;
    }
    if (tid == 0) g_nlist = 0u;
}

// ---------------- K1: lean bitmap filter + candidate insert ----------------
__device__ __noinline__ void insert_candidate(unsigned long long key) {
    unsigned long long h = mix64(key);          // recomputed on rare path
    unsigned idx = (unsigned)(h >> 32) & HMASK;
    unsigned long long tag = key | OCCBIT;
    for (;;) {
        unsigned long long cur = __ldcg(&g_hash[idx]);
        if (cur == 0ull) {
            unsigned long long old = atomicCAS(&g_hash[idx], 0ull, tag);
            if (old == 0ull) return;
            cur = old;
        }
        if (((cur ^ tag) & KEYMASK) == 0ull) return;   // already inserted
        idx = (idx + 1) & HMASK;
    }
}

__global__ void __launch_bounds__(256) k_filter(const float* __restrict__ x,
                                                const int* __restrict__ t) {
    const float4* x4 = reinterpret_cast<const float4*>(x);
    const int4*   t4 = reinterpret_cast<const int4*>(t);
    unsigned stride = gridDim.x * blockDim.x;
    unsigned i = blockIdx.x * blockDim.x + threadIdx.x;

    float4 xa, xb; int4 ta, tb;
    if (i < TOTAL / 8) {
        xa = __ldcs(x4 + 2 * i); xb = __ldcs(x4 + 2 * i + 1);
        ta = __ldcs(t4 + 2 * i); tb = __ldcs(t4 + 2 * i + 1);
    }
    for (; i < TOTAL / 8; i += stride) {
        unsigned b  = (i * 8u) / NN;       // 8-elem chunk never crosses batch
        unsigned gb = b * NCLS;
        float vs[8] = {xa.x, xa.y, xa.z, xa.w, xb.x, xb.y, xb.z, xb.w};
        int   cs[8] = {ta.x, ta.y, ta.z, ta.w, tb.x, tb.y, tb.z, tb.w};
        unsigned words[8], bits[8], olds[8];
#pragma unroll
        for (int j = 0; j < 8; j++) {
            unsigned long long h = mix64(make_key(gb, cs[j], vs[j]));
            unsigned bi = (unsigned)h & BITIDX_MASK;
            words[j] = bi >> 5;
            bits[j]  = 1u << (bi & 31);
        }
#pragma unroll
        for (int j = 0; j < 8; j++)
            olds[j] = atomicOr(&g_bitmap[words[j]], bits[j]);   // 8 in flight
        // prefetch next iteration's inputs under the atomic latency
        unsigned inext = i + stride;
        float4 nxa, nxb; int4 nta, ntb;
        if (inext < TOTAL / 8) {
            nxa = __ldcs(x4 + 2 * inext); nxb = __ldcs(x4 + 2 * inext + 1);
            nta = __ldcs(t4 + 2 * inext); ntb = __ldcs(t4 + 2 * inext + 1);
        }
#pragma unroll
        for (int j = 0; j < 8; j++)
            if (olds[j] & bits[j])
                insert_candidate(make_key(gb, cs[j], vs[j]));   // key recomputed
        xa = nxa; xb = nxb; ta = nta; tb = ntb;
    }
}

// ---------------- K2: pipelined probe/count + group stats ------------------
#define P3_TPB    128
#define P3_CHUNK  8192
#define BLKS_PER_B ((NN + P3_CHUNK - 1) / P3_CHUNK)   // 245

__device__ __forceinline__ void probe_resolve(unsigned long long key,
                                              unsigned idx,
                                              unsigned long long cur) {
    unsigned long long tag = key | OCCBIT;
    for (;;) {
        if (cur == 0ull) return;                       // not a candidate
        if (((cur ^ tag) & KEYMASK) == 0ull) {
            unsigned long long old = atomicAdd(&g_hash[idx], CNTONE);
            // exactly-once append when count transitions 1 -> 2 (true dup)
            if (((old >> 39) & 0xFFFFFFull) == 1ull) {
                unsigned pos = atomicAdd(&g_nlist, 1u);
                if (pos < LISTCAP) g_list[pos] = idx;
            }
            return;
        }
        idx = (idx + 1) & HMASK;
        cur = __ldg(&g_hash[idx]);
    }
}

__global__ void __launch_bounds__(P3_TPB) k_probe_stats(
    const float* __restrict__ x, const int* __restrict__ t) {
    // [class][thread] layout -> conflict-free for any class mix
    __shared__ float         s_sum[NCLS * P3_TPB];   // 8KB
    __shared__ unsigned char s_cnt[NCLS * P3_TPB];   // 2KB (<=64/thread)
    __shared__ unsigned int  s_min[NCLS * P3_TPB];   // 8KB

    const int tx = threadIdx.x;
    const int b  = blockIdx.y;
    const unsigned gbase = (unsigned)b * NCLS;

#pragma unroll
    for (int c = 0; c < NCLS; c++) {
        s_sum[c * P3_TPB + tx] = 0.f;
        s_cnt[c * P3_TPB + tx] = 0;
        s_min[c * P3_TPB + tx] = 0xFFFFFFFFu;
    }
    __syncthreads();

    long long base = (long long)b * NN + (long long)blockIdx.x * P3_CHUNK;
    int nelem = NN - blockIdx.x * P3_CHUNK;
    if (nelem > P3_CHUNK) nelem = P3_CHUNK;
    int nv = nelem >> 3;   // 8-wide batches

    const float4* x4 = reinterpret_cast<const float4*>(x + base);
    const int4*   t4 = reinterpret_cast<const int4*>(t + base);

    float4 xa, xb; int4 ta, tb;
    if (tx < nv) {
        xa = __ldcs(x4 + 2 * tx); xb = __ldcs(x4 + 2 * tx + 1);
        ta = __ldcs(t4 + 2 * tx); tb = __ldcs(t4 + 2 * tx + 1);
    }
    for (int i = tx; i < nv; i += P3_TPB) {
        float vs[8] = {xa.x, xa.y, xa.z, xa.w, xb.x, xb.y, xb.z, xb.w};
        int   cs[8] = {ta.x, ta.y, ta.z, ta.w, tb.x, tb.y, tb.z, tb.w};

        unsigned long long curs[8];
        unsigned idxs[8];
#pragma unroll
        for (int j = 0; j < 8; j++) {
            unsigned long long h = mix64(make_key(gbase, cs[j], vs[j]));
            idxs[j] = (unsigned)(h >> 32) & HMASK;
        }
#pragma unroll
        for (int j = 0; j < 8; j++)
            curs[j] = __ldg(&g_hash[idxs[j]]);         // 8 probes in flight

        // prefetch next iteration's inputs under probe latency
        int inext = i + P3_TPB;
        float4 nxa, nxb; int4 nta, ntb;
        if (inext < nv) {
            nxa = __ldcs(x4 + 2 * inext); nxb = __ldcs(x4 + 2 * inext + 1);
            nta = __ldcs(t4 + 2 * inext); ntb = __ldcs(t4 + 2 * inext + 1);
        }
#pragma unroll
        for (int j = 0; j < 8; j++) {
            // stats (conflict-free smem) hidden under probe latency
            int s = cs[j] * P3_TPB + tx;
            s_sum[s] += vs[j];
            s_cnt[s] = (unsigned char)(s_cnt[s] + 1);
            unsigned ov = orderf(__float_as_uint(vs[j]));
            if (ov < s_min[s]) s_min[s] = ov;
            probe_resolve(make_key(gbase, cs[j], vs[j]), idxs[j], curs[j]);
        }
        xa = nxa; xb = nxb; ta = nta; tb = ntb;
    }
    __syncthreads();

    // block reduce per class
    __shared__ float        r_sum[P3_TPB / 32][NCLS];
    __shared__ unsigned int r_cnt[P3_TPB / 32][NCLS];
    __shared__ unsigned int r_min[P3_TPB / 32][NCLS];
    const int lane = tx & 31, warp = tx >> 5;
#pragma unroll
    for (int c = 0; c < NCLS; c++) {
        float    sv = s_sum[c * P3_TPB + tx];
        unsigned cv = s_cnt[c * P3_TPB + tx];
        unsigned mv = s_min[c * P3_TPB + tx];
#pragma unroll
        for (int o = 16; o > 0; o >>= 1) {
            sv += __shfl_down_sync(0xFFFFFFFFu, sv, o);
            cv += __shfl_down_sync(0xFFFFFFFFu, cv, o);
            unsigned m2 = __shfl_down_sync(0xFFFFFFFFu, mv, o);
            mv = mv < m2 ? mv : m2;
        }
        if (lane == 0) { r_sum[warp][c] = sv; r_cnt[warp][c] = cv; r_min[warp][c] = mv; }
    }
    __syncthreads();
    if (tx < NCLS) {
        float    sv = 0.f; unsigned cv = 0u; unsigned mv = 0xFFFFFFFFu;
#pragma unroll
        for (int w = 0; w < P3_TPB / 32; w++) {
            sv += r_sum[w][tx];
            cv += r_cnt[w][tx];
            mv = mv < r_min[w][tx] ? mv : r_min[w][tx];
        }
        atomicAdd(&g_sum[gbase + tx], (double)sv);
        atomicAdd(&g_cntg[gbase + tx], cv);
        atomicMin(&g_minord[gbase + tx], mv);
    }
}

// ---------------- K3: modes from dup-list (smem pre-reduction) -------------
__device__ __forceinline__ void mode_update_s(unsigned long long cur,
                                              unsigned long long* s_pk) {
    unsigned cnt = (unsigned)((cur >> 39) & 0xFFFFFFu);
    if (cnt >= 2u) {
        unsigned grp = (unsigned)((cur >> 32) & 0x7Fu);
        unsigned u   = (unsigned)(cur & 0xFFFFFFFFull);
        unsigned ov  = orderf(u);
        unsigned long long packed =
            ((unsigned long long)cnt << 32) | (unsigned long long)(~ov);
        atomicMax(&s_pk[grp], packed);
    }
}

#define MODES_TPB 256
#define MODES_BLK 256

__global__ void __launch_bounds__(MODES_TPB) k_modes() {
    __shared__ unsigned long long s_pk[NGRP];
    if (threadIdx.x < NGRP) s_pk[threadIdx.x] = 0ull;
    __syncthreads();

    unsigned n = g_nlist;
    unsigned stride = gridDim.x * blockDim.x;
    if (n <= LISTCAP) {
        for (unsigned i = blockIdx.x * blockDim.x + threadIdx.x; i < n;
             i += stride)
            mode_update_s(__ldcg(&g_hash[g_list[i]]), s_pk);
    } else {
        // fallback: list overflowed -> scan the whole table (always correct)
        for (unsigned i = blockIdx.x * blockDim.x + threadIdx.x; i < HSLOTS;
             i += stride)
            mode_update_s(__ldcs(&g_hash[i]), s_pk);
    }
    __syncthreads();
    if (threadIdx.x < NGRP) {
        unsigned long long v = s_pk[threadIdx.x];
        if (v != 0ull) atomicMax(&g_packed[threadIdx.x], v);
    }
}

// ---------------- K4: final scalar ----------------
__global__ void k_final(float* __restrict__ out) {
    __shared__ double red[128];
    int g = threadIdx.x;
    double contrib = 0.0;
    if (g < NGRP) {
        unsigned cnt = g_cntg[g];
        if (cnt > 0u) {
            double mean = g_sum[g] / (double)cnt;
            unsigned long long packed = g_packed[g];
            unsigned ov;
            if (packed != 0ull) {
                ov = ~((unsigned)(packed & 0xFFFFFFFFull));   // dup mode
            } else {
                ov = g_minord[g];                              // all counts == 1
            }
            unsigned u = (ov & 0x80000000u) ? (ov ^ 0x80000000u) : ~ov;
            float mode = __uint_as_float(u);
            contrib = (double)cnt * (mean - (double)mode);
        }
    }
    red[threadIdx.x] = contrib;
    __syncthreads();
    for (int s = 64; s > 0; s >>= 1) {
        if (threadIdx.x < s) red[threadIdx.x] += red[threadIdx.x + s];
        __syncthreads();
    }
    if (threadIdx.x == 0) out[0] = (float)(red[0] / (double)TOTAL);
}

// ---------------- launch ----------------
extern "C" void kernel_launch(void* const* d_in, const int* in_sizes, int n_in,
                              void* d_out, int out_size) {
    const float* x = (const float*)d_in[0];
    const int*   t = (const int*)d_in[1];
    float* out = (float*)d_out;

    k_clear_bm<<<4096, 256>>>();
    k_clear_hash<<<8192, 256>>>();
    k_filter<<<8192, 256>>>(x, t);
    dim3 g3(BLKS_PER_B, BB);
    k_probe_stats<<<g3, P3_TPB>>>(x, t);      // 4th launch -> ncu captures this
    k_modes<<<MODES_BLK, MODES_TPB>>>();
    k_final<<<1, 128>>>(out);
}